// round 10
// baseline (speedup 1.0000x reference)
#include <cuda_runtime.h>
#include <math.h>

// ---------------------------------------------------------------------------
// PCGNN R10: project-then-select restructure.
//  K1: per-source score + sigmoid (unchanged)
//  K2: dense streaming projections  g_zs = x[:30000] @ W_self,
//                                   g_z  = x[:60000] @ W_neigh   (one kernel, 2 launches)
//  K3: warp-local select + mean-of-z + bias/relu + output projection (no barriers)
// Uses mean(sel_feat) @ W = mean(sel_feat @ W).
// Shapes: N_SRC=60000, N_DST=30000, DEG=32, F=128, E=64, C=2, K=16
// ---------------------------------------------------------------------------

#define F_DIM   128
#define E_DIM   64
#define DEG     32
#define KSEL    16
#define NBR     16         // rows per CTA-iteration in K2
#define THREADS 512

#define N_SRC_MAX 60000
#define N_DST_MAX 30000
__device__ float g_sig[N_SRC_MAX];           // sigmoid(x[v]·Wd0 + b0)
__device__ float g_z [N_SRC_MAX * E_DIM];    // x @ W_neigh   (15.4 MB)
__device__ float g_zs[N_DST_MAX * E_DIM];    // x_dst @ W_self (7.7 MB)

#define FMA2(d, a, b, c) \
    asm("fma.rn.f32x2 %0, %1, %2, %3;" : "=l"(d) : "l"(a), "l"(b), "l"(c))
#define LDS_V2U64(a, b, addr) \
    asm volatile("ld.shared.v2.u64 {%0, %1}, [%2];" : "=l"(a), "=l"(b) : "r"(addr))
#define PACKF2(o, lo, hi) \
    asm("mov.b64 %0, {%1, %2};" : "=l"(o) : "f"(lo), "f"(hi))
#define UNPACKF2(lo, hi, v) \
    asm("mov.b64 {%0, %1}, %2;" : "=f"(lo), "=f"(hi) : "l"(v))

// ---- K1: score precompute, one warp per source row ----------------------------
__global__ void score_kernel(const float* __restrict__ x,
                             const float* __restrict__ Wd,   // [128,2] row-major
                             const float* __restrict__ bd,   // [2]
                             float* __restrict__ score_out,  // [n_dst,2]
                             int n_src, int n_dst) {
    int w    = (blockIdx.x * blockDim.x + threadIdx.x) >> 5;
    int lane = threadIdx.x & 31;
    if (w >= n_src) return;
    int f0 = lane * 4;
    float4 xv = *(const float4*)(x + (size_t)w * F_DIM + f0);
    float4 wA = *(const float4*)(Wd + f0 * 2);
    float4 wB = *(const float4*)(Wd + f0 * 2 + 4);
    float d0 = xv.x*wA.x + xv.y*wA.z + xv.z*wB.x + xv.w*wB.z;
    float d1 = xv.x*wA.y + xv.y*wA.w + xv.z*wB.y + xv.w*wB.w;
    #pragma unroll
    for (int o = 16; o; o >>= 1) {
        d0 += __shfl_xor_sync(0xffffffffu, d0, o);
        d1 += __shfl_xor_sync(0xffffffffu, d1, o);
    }
    if (lane == 0) {
        float s0 = d0 + bd[0];
        g_sig[w] = 1.0f / (1.0f + expf(-s0));
        if (w < n_dst) {
            score_out[(size_t)w * 2]     = s0;
            score_out[(size_t)w * 2 + 1] = d1 + bd[1];
        }
    }
}

// ---- K2: out[r][e] = x[r] . W[:,e]  (streaming tiled GEMM) --------------------
// dynamic SMEM: sx[16*128] (8192 B) then spart[16*16*64] (65536 B) = 73728 B
#define K2_SX    0
#define K2_PART  8192
#define K2_TOTAL 73728

__global__ __launch_bounds__(THREADS, 2)
void proj_kernel(const float* __restrict__ x,
                 const float* __restrict__ W,    // [128,64] row-major
                 float* __restrict__ out,        // [n_rows,64]
                 int n_rows) {
    extern __shared__ char sm[];
    float* sx    = (float*)(sm + K2_SX);     // [row][f], stride 128
    float* spart = (float*)(sm + K2_PART);   // [sl][row][e]

    const int tid  = threadIdx.x;
    const int g    = tid >> 5;        // warp 0..15
    const int lane = tid & 31;
    const int ep   = tid & 31;        // e-pair: e = {2ep, 2ep+1}
    const int sl   = tid >> 5;        // f-slice 0..15 (8 f each)

    // weights for (sl, ep), f-paired as f32x2: 8 u64 = 16 regs
    unsigned long long ws0[4], ws1[4];
    {
        const int e0 = 2 * ep, e1 = e0 + 1;
        #pragma unroll
        for (int k = 0; k < 4; k++) {
            const int fa = sl * 8 + 2 * k, fb = fa + 1;
            PACKF2(ws0[k], W[fa * E_DIM + e0], W[fb * E_DIM + e0]);
            PACKF2(ws1[k], W[fa * E_DIM + e1], W[fb * E_DIM + e1]);
        }
    }
    const unsigned xbase = (unsigned)__cvta_generic_to_shared(sx) + sl * 32;

    // stage mapping: thread -> one float4 (row = tid/32, col4 = tid%32)
    const int srow = tid >> 5;
    const int scol = (tid & 31) * 4;

    for (int base = blockIdx.x * NBR; base < n_rows; base += gridDim.x * NBR) {
        // ---- stage 16 rows, coalesced ----
        {
            int r = base + srow;
            if (r >= n_rows) r = n_rows - 1;
            *(float4*)(sx + srow * F_DIM + scol) =
                *(const float4*)(x + (size_t)r * F_DIM + scol);
        }
        __syncthreads();

        // ---- compute: 16 rows x (8 f) x (2 e) per thread ----
        #pragma unroll
        for (int n = 0; n < NBR; n++) {
            const unsigned xa = xbase + n * (F_DIM * 4);
            unsigned long long x0, x1, x2, x3;
            LDS_V2U64(x0, x1, xa);
            LDS_V2U64(x2, x3, xa + 16);
            unsigned long long a0, a1;
            PACKF2(a0, 0.f, 0.f);
            PACKF2(a1, 0.f, 0.f);
            FMA2(a0, x0, ws0[0], a0);  FMA2(a1, x0, ws1[0], a1);
            FMA2(a0, x1, ws0[1], a0);  FMA2(a1, x1, ws1[1], a1);
            FMA2(a0, x2, ws0[2], a0);  FMA2(a1, x2, ws1[2], a1);
            FMA2(a0, x3, ws0[3], a0);  FMA2(a1, x3, ws1[3], a1);
            float lo, hi, p0, p1;
            UNPACKF2(lo, hi, a0);  p0 = lo + hi;
            UNPACKF2(lo, hi, a1);  p1 = lo + hi;
            *(float2*)(spart + (sl * NBR + n) * E_DIM + 2 * ep) =
                make_float2(p0, p1);
        }
        __syncthreads();

        // ---- reduce slices + store row base+g (warp-local) ----
        {
            float s0 = 0.f, s1 = 0.f;
            #pragma unroll
            for (int s = 0; s < 16; s++) {
                s0 += spart[(s * NBR + g) * E_DIM + lane];
                s1 += spart[(s * NBR + g) * E_DIM + lane + 32];
            }
            const int r = base + g;
            if (r < n_rows) {
                out[(size_t)r * E_DIM + lane]      = s0;
                out[(size_t)r * E_DIM + lane + 32] = s1;
            }
        }
        // no trailing barrier: next stage writes sx (D reads done before the
        // post-compute barrier); next compute writes spart only after the next
        // post-stage barrier, which follows every warp's reduce reads.
    }
}

// ---- K3: warp-local select + mean(z) + relu + output projection ---------------
__global__ __launch_bounds__(THREADS)
void out_kernel(const int*   __restrict__ neighbors,
                const float* __restrict__ b_sage,   // [64]
                const float* __restrict__ W_out,    // [64,2]
                const float* __restrict__ b_out,    // [2]
                float* __restrict__ out_logits,     // [n_dst,2]
                int n_dst) {
    __shared__ int ssel[16 * KSEL];
    const int tid  = threadIdx.x;
    const int g    = tid >> 5;
    const int lane = tid & 31;

    const float2 bs = *(const float2*)(b_sage + 2 * lane);      // b_sage[2l],[2l+1]
    const float4 wo = *(const float4*)(W_out + 4 * lane);       // rows 2l, 2l+1
    const float  bo0 = b_out[0], bo1 = b_out[1];

    for (int node = blockIdx.x * 16 + g; node < n_dst; node += gridDim.x * 16) {
        // select: top-16 smallest |sig(node) - sig(nb)|, stable tie-break
        int nb = neighbors[(size_t)node * DEG + lane];
        float t = g_sig[node];
        float d = fabsf(t - g_sig[nb]);
        int rank = 0;
        #pragma unroll
        for (int j = 0; j < 32; j++) {
            float dj = __shfl_sync(0xffffffffu, d, j);
            rank += (dj < d) || (dj == d && j < lane);
        }
        if (rank < KSEL) ssel[g * KSEL + rank] = nb;
        __syncwarp();

        // mean of 16 z-rows; lane covers e = 2l, 2l+1
        float a0 = 0.f, a1 = 0.f;
        #pragma unroll
        for (int k = 0; k < KSEL; k++) {
            int idx = ssel[g * KSEL + k];
            float2 v = *(const float2*)(g_z + (size_t)idx * E_DIM + 2 * lane);
            a0 += v.x;  a1 += v.y;
        }
        __syncwarp();   // ssel reads done before next iteration's writes

        float2 zs = *(const float2*)(g_zs + (size_t)node * E_DIM + 2 * lane);
        float h0 = fmaxf(fmaf(a0, 0.0625f, zs.x) + bs.x, 0.f);
        float h1 = fmaxf(fmaf(a1, 0.0625f, zs.y) + bs.y, 0.f);

        float c0 = h0 * wo.x + h1 * wo.z;
        float c1 = h0 * wo.y + h1 * wo.w;
        #pragma unroll
        for (int o = 16; o; o >>= 1) {
            c0 += __shfl_xor_sync(0xffffffffu, c0, o);
            c1 += __shfl_xor_sync(0xffffffffu, c1, o);
        }
        if (lane == 0) {
            out_logits[(size_t)node * 2]     = c0 + bo0;
            out_logits[(size_t)node * 2 + 1] = c1 + bo1;
        }
    }
}

extern "C" void kernel_launch(void* const* d_in, const int* in_sizes, int n_in,
                              void* d_out, int out_size) {
    const float* x        = (const float*)d_in[0];
    const int*   neighbors= (const int*)  d_in[1];
    const float* W_dist   = (const float*)d_in[2];
    const float* b_dist   = (const float*)d_in[3];
    const float* W_self   = (const float*)d_in[4];
    const float* W_neigh  = (const float*)d_in[5];
    const float* b_sage   = (const float*)d_in[6];
    const float* W_out    = (const float*)d_in[7];
    const float* b_out    = (const float*)d_in[8];

    const int n_src = in_sizes[0] / F_DIM;
    const int n_dst = in_sizes[1] / DEG;

    float* out    = (float*)d_out;
    float* logits = out;                     // [n_dst, 2]
    float* score  = out + (size_t)n_dst * 2; // [n_dst, 2]

    float* zs_ptr; cudaGetSymbolAddress((void**)&zs_ptr, g_zs);
    float* z_ptr;  cudaGetSymbolAddress((void**)&z_ptr,  g_z);

    // K1: per-source score + sigmoid
    int blocks1 = (n_src + 7) / 8;
    score_kernel<<<blocks1, 256>>>(x, W_dist, b_dist, score, n_src, n_dst);

    // K2: dense projections (streaming)
    cudaFuncSetAttribute(proj_kernel,
                         cudaFuncAttributeMaxDynamicSharedMemorySize, K2_TOTAL);
    proj_kernel<<<296, THREADS, K2_TOTAL>>>(x, W_self,  zs_ptr, n_dst);
    proj_kernel<<<296, THREADS, K2_TOTAL>>>(x, W_neigh, z_ptr,  n_src);

    // K3: select + combine + output (barrier-free)
    out_kernel<<<296, THREADS>>>(neighbors, b_sage, W_out, b_out, logits, n_dst);
}

// round 11
// speedup vs baseline: 1.0413x; 1.0413x over previous
#include <cuda_runtime.h>
#include <math.h>

// ---------------------------------------------------------------------------
// PCGNN R11: R9 + software pipeline — select/gather(i+1) overlapped with
// GEMM(i) via double-buffered staging (smem, not registers). 2 barriers/iter.
// 512 thr, NB=16, 2 CTAs/SM, FFMA2 Phase D.
// Shapes: N_SRC=60000, N_DST=30000, DEG=32, F=128, E=64, C=2, K=16
// ---------------------------------------------------------------------------

#define F_DIM   128
#define E_DIM   64
#define DEG     32
#define KSEL    16
#define NB      16         // nodes per block-iteration (= warps)
#define THREADS 512

#define N_SRC_MAX 60000
__device__ float g_sig[N_SRC_MAX];   // sigmoid(x[v]·Wd0 + b0) for every source row

#define FMA2(d, a, b, c) \
    asm("fma.rn.f32x2 %0, %1, %2, %3;" : "=l"(d) : "l"(a), "l"(b), "l"(c))
#define LDS_V2U64(a, b, addr) \
    asm volatile("ld.shared.v2.u64 {%0, %1}, [%2];" : "=l"(a), "=l"(b) : "r"(addr))
#define PACKF2(o, lo, hi) \
    asm("mov.b64 %0, {%1, %2};" : "=l"(o) : "f"(lo), "f"(hi))
#define UNPACKF2(lo, hi, v) \
    asm("mov.b64 {%0, %1}, %2;" : "=f"(lo), "=f"(hi) : "l"(v))

// ---- score precompute: one warp per source row --------------------------------
__global__ void score_kernel(const float* __restrict__ x,
                             const float* __restrict__ Wd,   // [128,2] row-major
                             const float* __restrict__ bd,   // [2]
                             float* __restrict__ score_out,  // [n_dst,2]
                             int n_src, int n_dst) {
    int w    = (blockIdx.x * blockDim.x + threadIdx.x) >> 5;
    int lane = threadIdx.x & 31;
    if (w >= n_src) return;
    int f0 = lane * 4;
    float4 xv = *(const float4*)(x + (size_t)w * F_DIM + f0);
    float4 wA = *(const float4*)(Wd + f0 * 2);
    float4 wB = *(const float4*)(Wd + f0 * 2 + 4);
    float d0 = xv.x*wA.x + xv.y*wA.z + xv.z*wB.x + xv.w*wB.z;
    float d1 = xv.x*wA.y + xv.y*wA.w + xv.z*wB.y + xv.w*wB.w;
    #pragma unroll
    for (int o = 16; o; o >>= 1) {
        d0 += __shfl_xor_sync(0xffffffffu, d0, o);
        d1 += __shfl_xor_sync(0xffffffffu, d1, o);
    }
    if (lane == 0) {
        float s0 = d0 + bd[0];
        g_sig[w] = 1.0f / (1.0f + expf(-s0));
        if (w < n_dst) {
            score_out[(size_t)w * 2]     = s0;
            score_out[(size_t)w * 2 + 1] = d1 + bd[1];
        }
    }
}

// ---- dynamic SMEM layout (bytes), all 16B-aligned -----------------------------
#define SM_XD0   0          // float [16*128]  x_dst  buf0                  8192
#define SM_XD1   8192       // float [16*128]  x_dst  buf1                  8192
#define SM_HN0   16384      // float [16*128]  h_neigh buf0                 8192
#define SM_HN1   24576      // float [16*128]  h_neigh buf1                 8192
#define SM_PART  32768      // float [16*16*64] partials [sl][n][e]        65536
#define SM_SEL   98304      // int   [16*16]   selected neighbor ids        1024
#define SM_TOTAL 99328

__global__ __launch_bounds__(THREADS, 2)
void pcgnn_main_kernel(const float* __restrict__ x,
                       const int*   __restrict__ neighbors,
                       const float* __restrict__ W_self,   // [128,64]
                       const float* __restrict__ W_neigh,  // [128,64]
                       const float* __restrict__ b_sage,   // [64]
                       const float* __restrict__ W_out,    // [64,2]
                       const float* __restrict__ b_out,    // [2]
                       float* __restrict__ out_logits,     // [n_dst,2]
                       int n_dst) {
    extern __shared__ char sm[];
    float*  spart = (float*) (sm + SM_PART);
    int*    ssel  = (int*)   (sm + SM_SEL);

    const int tid  = threadIdx.x;
    const int g    = tid >> 5;        // warp 0..15 (node slot / f-slice)
    const int lane = tid & 31;
    const int ep   = tid & 31;        // e-pair: e = {2ep, 2ep+1}   (Phase D)
    const int sl   = tid >> 5;        // f-slice 0..15 (8 f each)   (Phase D)

    // ---- loop-invariant weights, pre-packed as f32x2 over (evenf, oddf) ----
    unsigned long long ws0[4], wn0[4], ws1[4], wn1[4];
    {
        const int e0 = 2 * ep, e1 = e0 + 1;
        #pragma unroll
        for (int k = 0; k < 4; k++) {
            const int fa = sl * 8 + 2 * k, fb = fa + 1;
            PACKF2(ws0[k], W_self [fa * E_DIM + e0], W_self [fb * E_DIM + e0]);
            PACKF2(wn0[k], W_neigh[fa * E_DIM + e0], W_neigh[fb * E_DIM + e0]);
            PACKF2(ws1[k], W_self [fa * E_DIM + e1], W_self [fb * E_DIM + e1]);
            PACKF2(wn1[k], W_neigh[fa * E_DIM + e1], W_neigh[fb * E_DIM + e1]);
        }
    }
    // ---- loop-invariant reduce/output constants (registers) ----
    const float sbs0 = b_sage[lane];
    const float sbs1 = b_sage[lane + 32];
    const float2 wo0 = make_float2(W_out[lane * 2],        W_out[lane * 2 + 1]);
    const float2 wo1 = make_float2(W_out[(lane + 32) * 2], W_out[(lane + 32) * 2 + 1]);
    const float bo0 = b_out[0], bo1 = b_out[1];

    const unsigned smem0 = (unsigned)__cvta_generic_to_shared(sm);

    // ===== select + gather for node (sbase+g) into staging buffer `buf` =====
    auto selgather = [&](int sbase, int buf) {
        const int nodeg = sbase + g;
        const int node  = (nodeg < n_dst) ? nodeg : (n_dst - 1);
        float* xd = (float*)(sm + SM_XD0 + buf * 8192);
        float* hn = (float*)(sm + SM_HN0 + buf * 8192);

        // select: top-16 smallest |sig(node) - sig(nb)| via shfl rank
        int nb = neighbors[(unsigned)node * DEG + lane];
        float t = g_sig[node];
        float d = fabsf(t - g_sig[nb]);
        int rank = 0;
        #pragma unroll
        for (int j = 0; j < 32; j++) {
            float dj = __shfl_sync(0xffffffffu, d, j);
            rank += (dj < d) || (dj == d && j < lane);
        }
        if (rank < KSEL) ssel[g * KSEL + rank] = nb;
        __syncwarp();

        // gather: lane covers f = lane + 32*j, j=0..3 (coalesced per row)
        const int4* sp = (const int4*)(ssel + g * KSEL);
        int4 iA = sp[0], iB = sp[1], iC = sp[2], iD = sp[3];
        #pragma unroll
        for (int j = 0; j < 4; j++) {
            const int f = lane + 32 * j;
            float xdv = x[(unsigned)node * F_DIM + f];
            float s0, s1, s2, s3;
            s0  = x[(unsigned)iA.x * F_DIM + f];
            s1  = x[(unsigned)iA.y * F_DIM + f];
            s2  = x[(unsigned)iA.z * F_DIM + f];
            s3  = x[(unsigned)iA.w * F_DIM + f];
            s0 += x[(unsigned)iB.x * F_DIM + f];
            s1 += x[(unsigned)iB.y * F_DIM + f];
            s2 += x[(unsigned)iB.z * F_DIM + f];
            s3 += x[(unsigned)iB.w * F_DIM + f];
            s0 += x[(unsigned)iC.x * F_DIM + f];
            s1 += x[(unsigned)iC.y * F_DIM + f];
            s2 += x[(unsigned)iC.z * F_DIM + f];
            s3 += x[(unsigned)iC.w * F_DIM + f];
            s0 += x[(unsigned)iD.x * F_DIM + f];
            s1 += x[(unsigned)iD.y * F_DIM + f];
            s2 += x[(unsigned)iD.z * F_DIM + f];
            s3 += x[(unsigned)iD.w * F_DIM + f];
            hn[g * F_DIM + f] = ((s0 + s1) + (s2 + s3)) * 0.0625f;
            xd[g * F_DIM + f] = xdv;
        }
    };

    const int stride = gridDim.x * NB;
    const int base0  = blockIdx.x * NB;

    // ---- prologue: stage iteration 0 ----
    selgather(base0, 0);
    __syncthreads();
    int cur = 0;

    for (int base = base0; base < n_dst; base += stride) {
        // ===== region 1: select+gather(i+1) -> buf^1  ||  GEMM(i) <- buf =====
        selgather(base + stride, cur ^ 1);

        {   // Phase D: dual-GEMM with fma.rn.f32x2, f-paired
            const unsigned xbase = smem0 + SM_XD0 + cur * 8192 + sl * 32;
            const unsigned hbase = smem0 + SM_HN0 + cur * 8192 + sl * 32;
            #pragma unroll
            for (int n = 0; n < NB; n++) {
                const unsigned xa = xbase + n * (F_DIM * 4);
                const unsigned ha = hbase + n * (F_DIM * 4);
                unsigned long long x0, x1, x2, x3, h0, h1, h2, h3;
                LDS_V2U64(x0, x1, xa);
                LDS_V2U64(x2, x3, xa + 16);
                LDS_V2U64(h0, h1, ha);
                LDS_V2U64(h2, h3, ha + 16);
                unsigned long long a0, a1;
                PACKF2(a0, 0.f, 0.f);
                PACKF2(a1, 0.f, 0.f);
                FMA2(a0, x0, ws0[0], a0);  FMA2(a1, x0, ws1[0], a1);
                FMA2(a0, x1, ws0[1], a0);  FMA2(a1, x1, ws1[1], a1);
                FMA2(a0, x2, ws0[2], a0);  FMA2(a1, x2, ws1[2], a1);
                FMA2(a0, x3, ws0[3], a0);  FMA2(a1, x3, ws1[3], a1);
                FMA2(a0, h0, wn0[0], a0);  FMA2(a1, h0, wn1[0], a1);
                FMA2(a0, h1, wn0[1], a0);  FMA2(a1, h1, wn1[1], a1);
                FMA2(a0, h2, wn0[2], a0);  FMA2(a1, h2, wn1[2], a1);
                FMA2(a0, h3, wn0[3], a0);  FMA2(a1, h3, wn1[3], a1);
                float lo, hi, p0, p1;
                UNPACKF2(lo, hi, a0);  p0 = lo + hi;   // e = 2ep
                UNPACKF2(lo, hi, a1);  p1 = lo + hi;   // e = 2ep+1
                *(float2*)(spart + (sl * NB + n) * E_DIM + 2 * ep) =
                    make_float2(p0, p1);
            }
        }
        __syncthreads();   // spart complete; buf^1 staging complete

        // ===== region 2: reduce slices, bias+relu, project (warp-local) =====
        {
            const int nodeg = base + g;
            float s0 = 0.f, s1 = 0.f;
            #pragma unroll
            for (int s = 0; s < NB; s++) {
                s0 += spart[(s * NB + g) * E_DIM + lane];
                s1 += spart[(s * NB + g) * E_DIM + lane + 32];
            }
            float h0 = fmaxf(s0 + sbs0, 0.f);
            float h1 = fmaxf(s1 + sbs1, 0.f);
            float c0 = h0 * wo0.x + h1 * wo1.x;
            float c1 = h0 * wo0.y + h1 * wo1.y;
            #pragma unroll
            for (int o = 16; o; o >>= 1) {
                c0 += __shfl_xor_sync(0xffffffffu, c0, o);
                c1 += __shfl_xor_sync(0xffffffffu, c1, o);
            }
            if (lane == 0 && nodeg < n_dst) {
                out_logits[(size_t)nodeg * 2]     = c0 + bo0;
                out_logits[(size_t)nodeg * 2 + 1] = c1 + bo1;
            }
        }
        __syncthreads();   // R+E spart reads done before next D overwrites
        cur ^= 1;
    }
}

extern "C" void kernel_launch(void* const* d_in, const int* in_sizes, int n_in,
                              void* d_out, int out_size) {
    const float* x        = (const float*)d_in[0];
    const int*   neighbors= (const int*)  d_in[1];
    const float* W_dist   = (const float*)d_in[2];
    const float* b_dist   = (const float*)d_in[3];
    const float* W_self   = (const float*)d_in[4];
    const float* W_neigh  = (const float*)d_in[5];
    const float* b_sage   = (const float*)d_in[6];
    const float* W_out    = (const float*)d_in[7];
    const float* b_out    = (const float*)d_in[8];

    const int n_src = in_sizes[0] / F_DIM;
    const int n_dst = in_sizes[1] / DEG;

    float* out    = (float*)d_out;
    float* logits = out;                     // [n_dst, 2]
    float* score  = out + (size_t)n_dst * 2; // [n_dst, 2]

    int blocks1 = (n_src + 7) / 8;
    score_kernel<<<blocks1, 256>>>(x, W_dist, b_dist, score, n_src, n_dst);

    cudaFuncSetAttribute(pcgnn_main_kernel,
                         cudaFuncAttributeMaxDynamicSharedMemorySize, SM_TOTAL);
    pcgnn_main_kernel<<<296, THREADS, SM_TOTAL>>>(
        x, neighbors, W_self, W_neigh, b_sage, W_out, b_out, logits, n_dst);
}

// round 12
// speedup vs baseline: 1.3732x; 1.3187x over previous
#include <cuda_runtime.h>
#include <math.h>

// ---------------------------------------------------------------------------
// PCGNN R12: R9 + LDG.128 gather + f32x2 pair adds + cross-iteration
// neighbor/sigma prefetch. Single-buffer staging, 2 barriers/iteration.
// 512 thr, NB=16, 2 CTAs/SM, FFMA2 Phase D.
// Shapes: N_SRC=60000, N_DST=30000, DEG=32, F=128, E=64, C=2, K=16
// ---------------------------------------------------------------------------

#define F_DIM   128
#define E_DIM   64
#define DEG     32
#define KSEL    16
#define NB      16         // nodes per block-iteration (= warps)
#define THREADS 512

#define N_SRC_MAX 60000
__device__ float g_sig[N_SRC_MAX];   // sigmoid(x[v]·Wd0 + b0) for every source row

#define FMA2(d, a, b, c) \
    asm("fma.rn.f32x2 %0, %1, %2, %3;" : "=l"(d) : "l"(a), "l"(b), "l"(c))
#define ADD2(d, a, b) \
    asm("add.rn.f32x2 %0, %1, %2;" : "=l"(d) : "l"(a), "l"(b))
#define MUL2(d, a, b) \
    asm("mul.rn.f32x2 %0, %1, %2;" : "=l"(d) : "l"(a), "l"(b))
#define LDS_V2U64(a, b, addr) \
    asm volatile("ld.shared.v2.u64 {%0, %1}, [%2];" : "=l"(a), "=l"(b) : "r"(addr))
#define PACKF2(o, lo, hi) \
    asm("mov.b64 %0, {%1, %2};" : "=l"(o) : "f"(lo), "f"(hi))
#define UNPACKF2(lo, hi, v) \
    asm("mov.b64 {%0, %1}, %2;" : "=f"(lo), "=f"(hi) : "l"(v))

// ---- score precompute: one warp per source row --------------------------------
__global__ void score_kernel(const float* __restrict__ x,
                             const float* __restrict__ Wd,   // [128,2] row-major
                             const float* __restrict__ bd,   // [2]
                             float* __restrict__ score_out,  // [n_dst,2]
                             int n_src, int n_dst) {
    int w    = (blockIdx.x * blockDim.x + threadIdx.x) >> 5;
    int lane = threadIdx.x & 31;
    if (w >= n_src) return;
    int f0 = lane * 4;
    float4 xv = *(const float4*)(x + (size_t)w * F_DIM + f0);
    float4 wA = *(const float4*)(Wd + f0 * 2);
    float4 wB = *(const float4*)(Wd + f0 * 2 + 4);
    float d0 = xv.x*wA.x + xv.y*wA.z + xv.z*wB.x + xv.w*wB.z;
    float d1 = xv.x*wA.y + xv.y*wA.w + xv.z*wB.y + xv.w*wB.w;
    #pragma unroll
    for (int o = 16; o; o >>= 1) {
        d0 += __shfl_xor_sync(0xffffffffu, d0, o);
        d1 += __shfl_xor_sync(0xffffffffu, d1, o);
    }
    if (lane == 0) {
        float s0 = d0 + bd[0];
        g_sig[w] = 1.0f / (1.0f + expf(-s0));
        if (w < n_dst) {
            score_out[(size_t)w * 2]     = s0;
            score_out[(size_t)w * 2 + 1] = d1 + bd[1];
        }
    }
}

// ---- dynamic SMEM layout (bytes), all 16B-aligned -----------------------------
#define SM_XD    0          // float [16*128]    x_dst  [node][f]           8192
#define SM_HN    8192       // float [16*128]    h_neigh [node][f]          8192
#define SM_PART  16384      // float [16*16*64]  partials [sl][n][e]       65536
#define SM_SEL   81920      // int   [16*16]     selected neighbor ids      1024
#define SM_TOTAL 82944

__global__ __launch_bounds__(THREADS, 2)
void pcgnn_main_kernel(const float* __restrict__ x,
                       const int*   __restrict__ neighbors,
                       const float* __restrict__ W_self,   // [128,64]
                       const float* __restrict__ W_neigh,  // [128,64]
                       const float* __restrict__ b_sage,   // [64]
                       const float* __restrict__ W_out,    // [64,2]
                       const float* __restrict__ b_out,    // [2]
                       float* __restrict__ out_logits,     // [n_dst,2]
                       int n_dst) {
    extern __shared__ char sm[];
    float*  sxd   = (float*) (sm + SM_XD);   // [node][f], stride 128
    float*  shn   = (float*) (sm + SM_HN);   // [node][f], stride 128
    float*  spart = (float*) (sm + SM_PART);
    int*    ssel  = (int*)   (sm + SM_SEL);

    const int tid  = threadIdx.x;
    const int g    = tid >> 5;        // warp 0..15 (node slot / f-slice)
    const int lane = tid & 31;
    const int ep   = tid & 31;        // e-pair: e = {2ep, 2ep+1}   (Phase D)
    const int sl   = tid >> 5;        // f-slice 0..15 (8 f each)   (Phase D)
    const int fb   = lane * 4;        // gather f-quad base

    // ---- loop-invariant weights, pre-packed as f32x2 over (evenf, oddf) ----
    unsigned long long ws0[4], wn0[4], ws1[4], wn1[4];
    {
        const int e0 = 2 * ep, e1 = e0 + 1;
        #pragma unroll
        for (int k = 0; k < 4; k++) {
            const int fa = sl * 8 + 2 * k, fc = fa + 1;
            PACKF2(ws0[k], W_self [fa * E_DIM + e0], W_self [fc * E_DIM + e0]);
            PACKF2(wn0[k], W_neigh[fa * E_DIM + e0], W_neigh[fc * E_DIM + e0]);
            PACKF2(ws1[k], W_self [fa * E_DIM + e1], W_self [fc * E_DIM + e1]);
            PACKF2(wn1[k], W_neigh[fa * E_DIM + e1], W_neigh[fc * E_DIM + e1]);
        }
    }
    // ---- loop-invariant reduce/output constants (registers) ----
    const float sbs0 = b_sage[lane];
    const float sbs1 = b_sage[lane + 32];
    const float2 wo0 = make_float2(W_out[lane * 2],        W_out[lane * 2 + 1]);
    const float2 wo1 = make_float2(W_out[(lane + 32) * 2], W_out[(lane + 32) * 2 + 1]);
    const float bo0 = b_out[0], bo1 = b_out[1];
    unsigned long long c16;  PACKF2(c16, 0.0625f, 0.0625f);   // 1/16 packed

    const unsigned xbase = (unsigned)__cvta_generic_to_shared(sxd) + sl * 32;
    const unsigned hbase = (unsigned)__cvta_generic_to_shared(shn) + sl * 32;

    const int stride = gridDim.x * NB;
    const int base0  = blockIdx.x * NB;

    // ---- prologue: prefetch select inputs for iteration 0 ----
    int   nb_pf;  float t_pf, s_pf;
    {
        const int n0 = (base0 + g < n_dst) ? base0 + g : n_dst - 1;
        nb_pf = neighbors[(unsigned)n0 * DEG + lane];
        t_pf  = g_sig[n0];
        s_pf  = g_sig[nb_pf];
    }

    for (int base = base0; base < n_dst; base += stride) {
        const int nodeg = base + g;
        const int node  = (nodeg < n_dst) ? nodeg : (n_dst - 1);

        // ---- Phase A: select using prefetched values (near-zero latency) ----
        {
            float d = fabsf(t_pf - s_pf);
            int rank = 0;
            #pragma unroll
            for (int j = 0; j < 32; j++) {
                float dj = __shfl_sync(0xffffffffu, d, j);
                rank += (dj < d) || (dj == d && j < lane);
            }
            if (rank < KSEL) ssel[g * KSEL + rank] = nb_pf;
        }
        __syncwarp();

        // ---- prefetch iteration i+1: neighbors + own sigma (independent) ----
        {
            const int nn = (base + stride + g < n_dst) ? base + stride + g
                                                       : n_dst - 1;
            nb_pf = neighbors[(unsigned)nn * DEG + lane];
            t_pf  = g_sig[nn];
        }

        // ---- Phase C: gather 16 z-rows + x_dst via LDG.128, f32x2 adds ----
        {
            const int4* sp = (const int4*)(ssel + g * KSEL);
            int4 iA = sp[0], iB = sp[1], iC = sp[2], iD = sp[3];
            #define ROW(idx) (*(const ulonglong2*)(x + (unsigned)(idx) * F_DIM + fb))
            ulonglong2 xdv = ROW(node);
            ulonglong2 r0 = ROW(iA.x), r1 = ROW(iA.y), r2 = ROW(iA.z), r3 = ROW(iA.w);
            ulonglong2 r4 = ROW(iB.x), r5 = ROW(iB.y), r6 = ROW(iB.z), r7 = ROW(iB.w);
            unsigned long long aX, aY, bX, bY;
            ADD2(aX, r0.x, r1.x);  ADD2(aY, r0.y, r1.y);
            ADD2(bX, r2.x, r3.x);  ADD2(bY, r2.y, r3.y);
            ADD2(aX, aX, r4.x);    ADD2(aY, aY, r4.y);
            ADD2(bX, bX, r5.x);    ADD2(bY, bY, r5.y);
            ADD2(aX, aX, r6.x);    ADD2(aY, aY, r6.y);
            ADD2(bX, bX, r7.x);    ADD2(bY, bY, r7.y);
            ulonglong2 s0 = ROW(iC.x), s1 = ROW(iC.y), s2 = ROW(iC.z), s3 = ROW(iC.w);
            ulonglong2 s4 = ROW(iD.x), s5 = ROW(iD.y), s6 = ROW(iD.z), s7 = ROW(iD.w);
            ADD2(aX, aX, s0.x);    ADD2(aY, aY, s0.y);
            ADD2(bX, bX, s1.x);    ADD2(bY, bY, s1.y);
            ADD2(aX, aX, s2.x);    ADD2(aY, aY, s2.y);
            ADD2(bX, bX, s3.x);    ADD2(bY, bY, s3.y);
            ADD2(aX, aX, s4.x);    ADD2(aY, aY, s4.y);
            ADD2(bX, bX, s5.x);    ADD2(bY, bY, s5.y);
            ADD2(aX, aX, s6.x);    ADD2(aY, aY, s6.y);
            ADD2(bX, bX, s7.x);    ADD2(bY, bY, s7.y);
            ADD2(aX, aX, bX);      ADD2(aY, aY, bY);
            MUL2(aX, aX, c16);     MUL2(aY, aY, c16);
            ulonglong2 hv; hv.x = aX; hv.y = aY;
            *(ulonglong2*)(shn + g * F_DIM + fb) = hv;
            *(ulonglong2*)(sxd + g * F_DIM + fb) = xdv;
            #undef ROW
        }
        // dependent prefetch last: nb_pf returned long ago, no stall here
        s_pf = g_sig[nb_pf];
        __syncthreads();   // all staging visible to all warps

        // ---- Phase D: dual-GEMM with fma.rn.f32x2, f-paired ----
        {
            #pragma unroll
            for (int n = 0; n < NB; n++) {
                const unsigned xa = xbase + n * (F_DIM * 4);
                const unsigned ha = hbase + n * (F_DIM * 4);
                unsigned long long x0, x1, x2, x3, h0, h1, h2, h3;
                LDS_V2U64(x0, x1, xa);
                LDS_V2U64(x2, x3, xa + 16);
                LDS_V2U64(h0, h1, ha);
                LDS_V2U64(h2, h3, ha + 16);
                unsigned long long a0, a1;
                PACKF2(a0, 0.f, 0.f);
                PACKF2(a1, 0.f, 0.f);
                FMA2(a0, x0, ws0[0], a0);  FMA2(a1, x0, ws1[0], a1);
                FMA2(a0, x1, ws0[1], a0);  FMA2(a1, x1, ws1[1], a1);
                FMA2(a0, x2, ws0[2], a0);  FMA2(a1, x2, ws1[2], a1);
                FMA2(a0, x3, ws0[3], a0);  FMA2(a1, x3, ws1[3], a1);
                FMA2(a0, h0, wn0[0], a0);  FMA2(a1, h0, wn1[0], a1);
                FMA2(a0, h1, wn0[1], a0);  FMA2(a1, h1, wn1[1], a1);
                FMA2(a0, h2, wn0[2], a0);  FMA2(a1, h2, wn1[2], a1);
                FMA2(a0, h3, wn0[3], a0);  FMA2(a1, h3, wn1[3], a1);
                float lo, hi, p0, p1;
                UNPACKF2(lo, hi, a0);  p0 = lo + hi;   // e = 2ep
                UNPACKF2(lo, hi, a1);  p1 = lo + hi;   // e = 2ep+1
                *(float2*)(spart + (sl * NB + n) * E_DIM + 2 * ep) =
                    make_float2(p0, p1);
            }
        }
        __syncthreads();   // spart complete

        // ---- Phase R+E (warp-local): reduce slices, bias+relu, project ----
        {
            float s0 = 0.f, s1 = 0.f;
            #pragma unroll
            for (int s = 0; s < NB; s++) {
                s0 += spart[(s * NB + g) * E_DIM + lane];
                s1 += spart[(s * NB + g) * E_DIM + lane + 32];
            }
            float h0 = fmaxf(s0 + sbs0, 0.f);
            float h1 = fmaxf(s1 + sbs1, 0.f);
            float c0 = h0 * wo0.x + h1 * wo1.x;
            float c1 = h0 * wo0.y + h1 * wo1.y;
            #pragma unroll
            for (int o = 16; o; o >>= 1) {
                c0 += __shfl_xor_sync(0xffffffffu, c0, o);
                c1 += __shfl_xor_sync(0xffffffffu, c1, o);
            }
            if (lane == 0 && nodeg < n_dst) {
                out_logits[(size_t)nodeg * 2]     = c0 + bo0;
                out_logits[(size_t)nodeg * 2 + 1] = c1 + bo1;
            }
        }
        // no trailing barrier (R9-proven):
        //  - next A writes ssel (warp-private, last read in own C phase);
        //  - next C writes sxd/shn — all D(i) reads done before post-D barrier;
        //  - next D writes spart only after next post-C barrier, which follows
        //    every warp's R+E spart reads.
    }
}

extern "C" void kernel_launch(void* const* d_in, const int* in_sizes, int n_in,
                              void* d_out, int out_size) {
    const float* x        = (const float*)d_in[0];
    const int*   neighbors= (const int*)  d_in[1];
    const float* W_dist   = (const float*)d_in[2];
    const float* b_dist   = (const float*)d_in[3];
    const float* W_self   = (const float*)d_in[4];
    const float* W_neigh  = (const float*)d_in[5];
    const float* b_sage   = (const float*)d_in[6];
    const float* W_out    = (const float*)d_in[7];
    const float* b_out    = (const float*)d_in[8];

    const int n_src = in_sizes[0] / F_DIM;
    const int n_dst = in_sizes[1] / DEG;

    float* out    = (float*)d_out;
    float* logits = out;                     // [n_dst, 2]
    float* score  = out + (size_t)n_dst * 2; // [n_dst, 2]

    int blocks1 = (n_src + 7) / 8;
    score_kernel<<<blocks1, 256>>>(x, W_dist, b_dist, score, n_src, n_dst);

    cudaFuncSetAttribute(pcgnn_main_kernel,
                         cudaFuncAttributeMaxDynamicSharedMemorySize, SM_TOTAL);
    pcgnn_main_kernel<<<296, THREADS, SM_TOTAL>>>(
        x, neighbors, W_self, W_neigh, b_sage, W_out, b_out, logits, n_dst);
}